// round 9
// baseline (speedup 1.0000x reference)
#include <cuda_runtime.h>
#include <cuda_fp16.h>
#include <cstdint>

#define NV 50000
#define NE 800000
#define FIN 128
#define FH  128
#define FO  64

// ---------------- scratch (no allocs allowed) ----------------
static __device__ int  g_deg   [NV];
static __device__ int  g_rowptr[NV + 1];
static __device__ int  g_cursor[NV];
static __device__ int2 g_col2  [NE];     // (src, dinv[src] bits)
static __device__ __align__(16) __half g_hp1[(size_t)NV * FH];   // x@W1      (fp16, unscaled)
static __device__ __align__(16) __half g_h1 [(size_t)NV * FH];   // layer-1 activation (fp16)
static __device__ __align__(16) __half g_hp2[(size_t)NV * FO];   // h1@W2     (fp16, unscaled)

// ---------------- inline edge-index dtype probe ----------------
// If edge_index is int64 (LE, values < 2^31), every odd int32 word is 0.
__device__ __forceinline__ int probe_is64(const int* __restrict__ raw) {
    __shared__ int anynz;
    if (threadIdx.x == 0) anynz = 0;
    __syncthreads();
    if (threadIdx.x < 256) {
        int v = __ldg(&raw[2 * threadIdx.x + 1]);
        if (v != 0) atomicOr(&anynz, 1);
    }
    __syncthreads();
    return anynz == 0;
}

// count dst degrees straight from raw edge buffer (deg pre-zeroed)
__global__ void count_deg_kernel(const int* __restrict__ raw, int e, int* __restrict__ deg) {
    int is64 = probe_is64(raw);
    int i = blockIdx.x * blockDim.x + threadIdx.x;
    if (i >= e) return;
    int d = is64 ? raw[2 * ((size_t)e + i)] : raw[(size_t)e + i];
    atomicAdd(&deg[d], 1);
}

// ---------------- single-block fused scan: rowptr + cursor ----------------
__global__ void scan_fused_kernel(const int* __restrict__ deg, int n,
                                  int* __restrict__ rowptr, int* __restrict__ cursor)
{
    __shared__ int sm[1024];
    const int CH = (n + 1023) / 1024;
    const int t  = threadIdx.x;
    const int lo = t * CH;
    const int hi = (lo + CH < n) ? lo + CH : n;

    int s = 0;
    for (int i = lo; i < hi; i++) s += deg[i];
    sm[t] = s;
    __syncthreads();
    for (int off = 1; off < 1024; off <<= 1) {
        int v = (t >= off) ? sm[t - off] : 0;
        __syncthreads();
        sm[t] += v;
        __syncthreads();
    }
    int pre = sm[t] - s;
    for (int i = lo; i < hi; i++) {
        int d = deg[i];
        rowptr[i] = pre;
        cursor[i] = pre;
        pre += d;
    }
    if (t == 1023) rowptr[n] = sm[1023];
}

// ---------------- CSR fill: col2[pos] = (src, dinv[src]) grouped by dst ----------------
__global__ void fill_kernel(const int* __restrict__ raw, int e,
                            const int* __restrict__ deg,
                            int* __restrict__ cursor, int2* __restrict__ col2)
{
    int is64 = probe_is64(raw);
    int i = blockIdx.x * blockDim.x + threadIdx.x;
    if (i >= e) return;
    int s, d;
    if (is64) {
        s = raw[2 * (size_t)i];
        d = raw[2 * ((size_t)e + i)];
    } else {
        s = raw[i];
        d = raw[(size_t)e + i];
    }
    float dv = rsqrtf((float)(__ldg(&deg[s]) + 1));
    int pos = atomicAdd(&cursor[d], 1);
    col2[pos] = make_int2(s, __float_as_int(dv));
}

// ---------------- tf32 mma helpers ----------------
__device__ __forceinline__ uint32_t f2tf(float f) {
    uint32_t r;
    asm("cvt.rna.tf32.f32 %0, %1;" : "=r"(r) : "f"(f));
    return r;
}
__device__ __forceinline__ void mma_tf32(float* d,
    uint32_t a0, uint32_t a1, uint32_t a2, uint32_t a3,
    uint32_t b0, uint32_t b1)
{
    asm volatile("mma.sync.aligned.m16n8k8.row.col.f32.tf32.tf32.f32 "
        "{%0,%1,%2,%3}, {%4,%5,%6,%7}, {%8,%9}, {%0,%1,%2,%3};"
        : "+f"(d[0]), "+f"(d[1]), "+f"(d[2]), "+f"(d[3])
        : "r"(a0), "r"(a1), "r"(a2), "r"(a3), "r"(b0), "r"(b1));
}

// ---------------- tensor-core GEMM: hp[row] = fp16( A[row] @ W )  (unscaled) ----------------
// Block tile 128 x OUT, K=128, 8 warps. A fp32 or fp16 per IN_HALF.
template<int OUT, bool IN_HALF>
__global__ __launch_bounds__(256) void gemm_tc_kernel(
    const void* __restrict__ Ain, const float* __restrict__ W,
    __half* __restrict__ hp, int n)
{
    constexpr int K       = 128;
    constexpr int WARPS_M = (OUT == 128) ? 2 : 4;
    constexpr int WARPS_N = 8 / WARPS_M;
    constexpr int WM      = 128 / WARPS_M;
    constexpr int WN      = OUT / WARPS_N;
    constexpr int MT      = WM / 16;
    constexpr int NT      = WN / 8;
    constexpr int SX      = K + 4;
    constexpr int SW      = OUT + 4;

    extern __shared__ uint32_t smem[];
    uint32_t* Xs = smem;               // [128][SX] tf32
    uint32_t* Ws = smem + 128 * SX;    // [K][SW]   tf32

    const int t    = threadIdx.x;
    const int lane = t & 31;
    const int wid  = t >> 5;
    const int wm   = wid % WARPS_M;
    const int wn   = wid / WARPS_M;
    const int lr   = lane >> 2;
    const int lc   = lane & 3;

    const int row0 = blockIdx.x * 128;

    for (int i = t; i < K * (OUT / 4); i += 256) {
        int r  = i / (OUT / 4);
        int c4 = i % (OUT / 4);
        float4 v = ((const float4*)W)[(size_t)r * (OUT / 4) + c4];
        uint32_t* p = &Ws[r * SW + c4 * 4];
        p[0] = f2tf(v.x); p[1] = f2tf(v.y); p[2] = f2tf(v.z); p[3] = f2tf(v.w);
    }
    if (IN_HALF) {
        const uint4* A8 = (const uint4*)Ain;
        for (int i = t; i < 128 * (K / 8); i += 256) {
            int r  = i / (K / 8);
            int c8 = i % (K / 8);
            int gr = row0 + r;
            uint32_t* p = &Xs[r * SX + c8 * 8];
            if (gr < n) {
                uint4 v = A8[(size_t)gr * (K / 8) + c8];
                const __half2* ph = (const __half2*)&v;
#pragma unroll
                for (int j = 0; j < 4; j++) {
                    float2 f = __half22float2(ph[j]);
                    p[2 * j]     = f2tf(f.x);
                    p[2 * j + 1] = f2tf(f.y);
                }
            } else {
#pragma unroll
                for (int j = 0; j < 8; j++) p[j] = 0;
            }
        }
    } else {
        const float4* A4 = (const float4*)Ain;
        for (int i = t; i < 128 * (K / 4); i += 256) {
            int r  = i / (K / 4);
            int c4 = i % (K / 4);
            int gr = row0 + r;
            float4 v = (gr < n) ? A4[(size_t)gr * (K / 4) + c4]
                                : make_float4(0.f, 0.f, 0.f, 0.f);
            uint32_t* p = &Xs[r * SX + c4 * 4];
            p[0] = f2tf(v.x); p[1] = f2tf(v.y); p[2] = f2tf(v.z); p[3] = f2tf(v.w);
        }
    }
    __syncthreads();

    float d[MT][NT][4];
#pragma unroll
    for (int mt = 0; mt < MT; mt++)
#pragma unroll
        for (int nt = 0; nt < NT; nt++) {
            d[mt][nt][0] = 0.f; d[mt][nt][1] = 0.f;
            d[mt][nt][2] = 0.f; d[mt][nt][3] = 0.f;
        }

    const int r0 = wm * WM;
    const int c0 = wn * WN;

#pragma unroll
    for (int k0 = 0; k0 < K; k0 += 8) {
        uint32_t b[NT][2];
#pragma unroll
        for (int nt = 0; nt < NT; nt++) {
            int bc = c0 + nt * 8 + lr;
            b[nt][0] = Ws[(k0 + lc)     * SW + bc];
            b[nt][1] = Ws[(k0 + lc + 4) * SW + bc];
        }
#pragma unroll
        for (int mt = 0; mt < MT; mt++) {
            int ar = r0 + mt * 16 + lr;
            uint32_t a0 = Xs[ar       * SX + k0 + lc];
            uint32_t a1 = Xs[(ar + 8) * SX + k0 + lc];
            uint32_t a2 = Xs[ar       * SX + k0 + lc + 4];
            uint32_t a3 = Xs[(ar + 8) * SX + k0 + lc + 4];
#pragma unroll
            for (int nt = 0; nt < NT; nt++)
                mma_tf32(d[mt][nt], a0, a1, a2, a3, b[nt][0], b[nt][1]);
        }
    }

#pragma unroll
    for (int mt = 0; mt < MT; mt++) {
        int gr0 = row0 + r0 + mt * 16 + lr;
        int gr1 = gr0 + 8;
#pragma unroll
        for (int nt = 0; nt < NT; nt++) {
            int gc = c0 + nt * 8 + 2 * lc;
            if (gr0 < n) {
                __half2 h = __floats2half2_rn(d[mt][nt][0], d[mt][nt][1]);
                ((uint32_t*)hp)[(size_t)gr0 * (OUT / 2) + gc / 2] = *(uint32_t*)&h;
            }
            if (gr1 < n) {
                __half2 h = __floats2half2_rn(d[mt][nt][2], d[mt][nt][3]);
                ((uint32_t*)hp)[(size_t)gr1 * (OUT / 2) + gc / 2] = *(uint32_t*)&h;
            }
        }
    }
}

// ---------------- aggregate: out[d] = act( dinv[d]*(dinv[d]*hp[d] + sum dv_s*hp[s]) + b ) ----------------
__device__ __forceinline__ void acc8s(float* a, uint4 v, float dv) {
    const __half2* ph = (const __half2*)&v;
#pragma unroll
    for (int j = 0; j < 4; j++) {
        float2 f = __half22float2(ph[j]);
        a[2 * j]     = fmaf(f.x, dv, a[2 * j]);
        a[2 * j + 1] = fmaf(f.y, dv, a[2 * j + 1]);
    }
}

template<int F, bool RELU, bool OUT_HALF>
__global__ __launch_bounds__(256) void aggregate_kernel(
    const int* __restrict__ rowptr, const int2* __restrict__ col2,
    const __half* __restrict__ hp, const int* __restrict__ deg,
    const float* __restrict__ b, void* __restrict__ out, int n)
{
    constexpr int LPR = F / 8;        // lanes per node row (16 or 8)
    constexpr int SUB = 32 / LPR;     // nodes per warp (2 or 4)
    const int warp = (blockIdx.x * blockDim.x + threadIdx.x) >> 5;
    const int lane = threadIdx.x & 31;
    const int node = warp * SUB + lane / LPR;
    const int li   = lane % LPR;
    if (node >= n) return;

    const uint4* hp4 = (const uint4*)hp;

    float a0[8] = {0,0,0,0,0,0,0,0};
    float a1[8] = {0,0,0,0,0,0,0,0};

    float dvn = rsqrtf((float)(__ldg(&deg[node]) + 1));
    acc8s(a0, hp4[(size_t)node * LPR + li], dvn);   // self-loop term

    int e  = rowptr[node];
    int e1 = rowptr[node + 1];

    for (; e + 8 <= e1; e += 8) {
        int2 c[8];
        uint4 v[8];
#pragma unroll
        for (int j = 0; j < 8; j++) c[j] = __ldg(&col2[e + j]);
#pragma unroll
        for (int j = 0; j < 8; j++) v[j] = hp4[(size_t)c[j].x * LPR + li];
#pragma unroll
        for (int j = 0; j < 8; j++)
            acc8s((j & 1) ? a1 : a0, v[j], __int_as_float(c[j].y));
    }
    for (; e < e1; e++) {
        int2 c = __ldg(&col2[e]);
        acc8s(a0, hp4[(size_t)c.x * LPR + li], __int_as_float(c.y));
    }
#pragma unroll
    for (int j = 0; j < 8; j++) a0[j] += a1[j];

    const float4* b4 = (const float4*)b;
    float4 bv0 = b4[li * 2];
    float4 bv1 = b4[li * 2 + 1];
    float o[8];
    o[0] = fmaf(a0[0], dvn, bv0.x);
    o[1] = fmaf(a0[1], dvn, bv0.y);
    o[2] = fmaf(a0[2], dvn, bv0.z);
    o[3] = fmaf(a0[3], dvn, bv0.w);
    o[4] = fmaf(a0[4], dvn, bv1.x);
    o[5] = fmaf(a0[5], dvn, bv1.y);
    o[6] = fmaf(a0[6], dvn, bv1.z);
    o[7] = fmaf(a0[7], dvn, bv1.w);
    if (RELU) {
#pragma unroll
        for (int j = 0; j < 8; j++) o[j] = fmaxf(o[j], 0.f);
    }
    if (OUT_HALF) {
        uint4 pk;
        __half2 h0 = __floats2half2_rn(o[0], o[1]);
        __half2 h1 = __floats2half2_rn(o[2], o[3]);
        __half2 h2 = __floats2half2_rn(o[4], o[5]);
        __half2 h3 = __floats2half2_rn(o[6], o[7]);
        pk.x = *(uint32_t*)&h0; pk.y = *(uint32_t*)&h1;
        pk.z = *(uint32_t*)&h2; pk.w = *(uint32_t*)&h3;
        ((uint4*)out)[(size_t)node * LPR + li] = pk;
    } else {
        float4* out4 = (float4*)out;
        out4[(size_t)node * (F / 4) + li * 2]     = make_float4(o[0], o[1], o[2], o[3]);
        out4[(size_t)node * (F / 4) + li * 2 + 1] = make_float4(o[4], o[5], o[6], o[7]);
    }
}

// ---------------- launcher ----------------
extern "C" void kernel_launch(void* const* d_in, const int* in_sizes, int n_in,
                              void* d_out, int out_size)
{
    const float* x   = (const float*)d_in[0];
    const int*   ei  = (const int*)d_in[1];     // int32 OR int64 raw words (probed per-block)
    const float* W1  = (const float*)d_in[2];
    const float* b1  = (const float*)d_in[3];
    const float* W2  = (const float*)d_in[4];
    const float* b2  = (const float*)d_in[5];
    float*       out = (float*)d_out;

    const int n = in_sizes[0] / FIN;   // 50000
    const int e = in_sizes[1] / 2;     // 800000

    void *p_deg, *p_rowptr, *p_cursor, *p_col2, *p_hp1, *p_h1, *p_hp2;
    cudaGetSymbolAddress(&p_deg,    g_deg);
    cudaGetSymbolAddress(&p_rowptr, g_rowptr);
    cudaGetSymbolAddress(&p_cursor, g_cursor);
    cudaGetSymbolAddress(&p_col2,   g_col2);
    cudaGetSymbolAddress(&p_hp1,    g_hp1);
    cudaGetSymbolAddress(&p_h1,     g_h1);
    cudaGetSymbolAddress(&p_hp2,    g_hp2);
    int*    deg    = (int*)p_deg;
    int*    rowptr = (int*)p_rowptr;
    int*    cursor = (int*)p_cursor;
    int2*   col2   = (int2*)p_col2;
    __half* hp1    = (__half*)p_hp1;
    __half* h1     = (__half*)p_h1;
    __half* hp2    = (__half*)p_hp2;

    // one-time side stream + events (created on first, non-captured, call)
    static cudaStream_t s_side = nullptr;
    static cudaEvent_t  ev_fork = nullptr, ev_join = nullptr;
    if (s_side == nullptr) {
        cudaStreamCreateWithFlags(&s_side, cudaStreamNonBlocking);
        cudaEventCreateWithFlags(&ev_fork, cudaEventDisableTiming);
        cudaEventCreateWithFlags(&ev_join, cudaEventDisableTiming);
    }

    const int smem1 = (128 * (128 + 4) + 128 * (FH + 4)) * (int)sizeof(uint32_t);
    const int smem2 = (128 * (128 + 4) + 128 * (FO + 4)) * (int)sizeof(uint32_t);
    cudaFuncSetAttribute((const void*)gemm_tc_kernel<FH, false>, cudaFuncAttributeMaxDynamicSharedMemorySize, smem1);
    cudaFuncSetAttribute((const void*)gemm_tc_kernel<FO, true>,  cudaFuncAttributeMaxDynamicSharedMemorySize, smem2);

    // ---- fork: entire CSR chain on side stream ----
    cudaEventRecord(ev_fork, 0);
    cudaStreamWaitEvent(s_side, ev_fork, 0);
    cudaMemsetAsync(deg, 0, n * sizeof(int), s_side);
    count_deg_kernel<<<(e + 255) / 256, 256, 0, s_side>>>(ei, e, deg);
    scan_fused_kernel<<<1, 1024, 0, s_side>>>(deg, n, rowptr, cursor);
    fill_kernel      <<<(e + 255) / 256, 256, 0, s_side>>>(ei, e, deg, cursor, col2);
    cudaEventRecord(ev_join, s_side);

    // ---- main: gemm1 (no dependencies at all) ----
    gemm_tc_kernel<FH, false><<<(n + 127) / 128, 256, smem1>>>(x, W1, hp1, n);

    // ---- join, then agg1 / gemm2 / agg2 ----
    cudaStreamWaitEvent(0, ev_join, 0);
    {
        int warps = (n + 1) / 2;
        aggregate_kernel<FH, true, true><<<(warps * 32 + 255) / 256, 256>>>(rowptr, col2, hp1, deg, b1, h1, n);
    }
    gemm_tc_kernel<FO, true><<<(n + 127) / 128, 256, smem2>>>(h1, W2, hp2, n);
    {
        int warps = (n + 3) / 4;
        aggregate_kernel<FO, false, false><<<(warps * 32 + 255) / 256, 256>>>(rowptr, col2, hp2, deg, b2, out, n);
    }
}

// round 10
// speedup vs baseline: 1.6191x; 1.6191x over previous
#include <cuda_runtime.h>
#include <cuda_fp16.h>
#include <cstdint>

#define NV 50000
#define NE 800000
#define FIN 128
#define FH  128
#define FO  64

// ---------------- scratch (no allocs allowed) ----------------
static __device__ int    g_is64;
static __device__ int    g_deg   [NV];
static __device__ int    g_rowptr[NV + 1];
static __device__ int    g_cursor[NV];
static __device__ int    g_col   [NE];
static __device__ int    g_part  [256];
static __device__ __align__(16) __half g_hp1[(size_t)NV * FH];   // dinv-prescaled x@W1   (fp16)
static __device__ __align__(16) float  g_h1 [(size_t)NV * FH];   // layer-1 activation    (fp32)
static __device__ __align__(16) __half g_hp2[(size_t)NV * FO];   // dinv-prescaled h1@W2  (fp16)

// ---------------- edge-index dtype probe ----------------
// If edge_index is int64 (LE, values < 2^31), every odd int32 word is 0.
__global__ void probe_kernel(const int* __restrict__ raw, int* __restrict__ is64) {
    int v = raw[2 * threadIdx.x + 1];
    int any = __syncthreads_or(v != 0);
    if (threadIdx.x == 0) *is64 = (any == 0) ? 1 : 0;
}

// count dst degrees straight from raw edge buffer (deg pre-zeroed)
__global__ void count_deg_kernel(const int* __restrict__ raw, int e,
                                 const int* __restrict__ is64f,
                                 int* __restrict__ deg) {
    int i = blockIdx.x * blockDim.x + threadIdx.x;
    if (i >= e) return;
    int d = (*is64f) ? raw[2 * ((size_t)e + i)] : raw[(size_t)e + i];
    atomicAdd(&deg[d], 1);
}

// ---------------- 3-phase scan ----------------
__global__ void scan_block_kernel(const int* __restrict__ deg, int n,
                                  int* __restrict__ rowptr, int* __restrict__ part)
{
    __shared__ int sm[1024];
    int i = blockIdx.x * 1024 + threadIdx.x;
    int v = (i < n) ? deg[i] : 0;
    sm[threadIdx.x] = v;
    __syncthreads();
    for (int off = 1; off < 1024; off <<= 1) {
        int t = (threadIdx.x >= (unsigned)off) ? sm[threadIdx.x - off] : 0;
        __syncthreads();
        sm[threadIdx.x] += t;
        __syncthreads();
    }
    if (i < n) rowptr[i] = sm[threadIdx.x] - v;      // block-local exclusive
    if (threadIdx.x == 1023) part[blockIdx.x] = sm[1023];
}

__global__ void scan_part_kernel(int* __restrict__ part, int nb,
                                 int* __restrict__ rowptr, int n)
{
    __shared__ int sm[256];
    int v = (threadIdx.x < (unsigned)nb) ? part[threadIdx.x] : 0;
    sm[threadIdx.x] = v;
    __syncthreads();
    for (int off = 1; off < 256; off <<= 1) {
        int t = (threadIdx.x >= (unsigned)off) ? sm[threadIdx.x - off] : 0;
        __syncthreads();
        sm[threadIdx.x] += t;
        __syncthreads();
    }
    if (threadIdx.x < (unsigned)nb) part[threadIdx.x] = sm[threadIdx.x] - v;  // exclusive
    if (threadIdx.x == 0) rowptr[n] = sm[255];
}

__global__ void add_off_kernel(const int* __restrict__ part, int n,
                               int* __restrict__ rowptr, int* __restrict__ cursor)
{
    int i = blockIdx.x * blockDim.x + threadIdx.x;
    if (i < n) {
        int r = rowptr[i] + part[i >> 10];
        rowptr[i] = r;
        cursor[i] = r;
    }
}

// ---------------- CSR fill: col[pos] = src, grouped by dst ----------------
__global__ void fill_kernel(const int* __restrict__ raw, int e,
                            const int* __restrict__ is64f,
                            int* __restrict__ cursor, int* __restrict__ col)
{
    int i = blockIdx.x * blockDim.x + threadIdx.x;
    if (i >= e) return;
    int s, d;
    if (*is64f) {
        s = raw[2 * (size_t)i];
        d = raw[2 * ((size_t)e + i)];
    } else {
        s = raw[i];
        d = raw[(size_t)e + i];
    }
    int pos = atomicAdd(&cursor[d], 1);
    col[pos] = s;
}

// ---------------- tf32 mma helpers ----------------
__device__ __forceinline__ uint32_t f2tf(float f) {
    uint32_t r;
    asm("cvt.rna.tf32.f32 %0, %1;" : "=r"(r) : "f"(f));
    return r;
}
__device__ __forceinline__ void mma_tf32(float* d,
    uint32_t a0, uint32_t a1, uint32_t a2, uint32_t a3,
    uint32_t b0, uint32_t b1)
{
    asm volatile("mma.sync.aligned.m16n8k8.row.col.f32.tf32.tf32.f32 "
        "{%0,%1,%2,%3}, {%4,%5,%6,%7}, {%8,%9}, {%0,%1,%2,%3};"
        : "+f"(d[0]), "+f"(d[1]), "+f"(d[2]), "+f"(d[3])
        : "r"(a0), "r"(a1), "r"(a2), "r"(a3), "r"(b0), "r"(b1));
}

// ---------------- tensor-core GEMM: hp[row] = fp16( dinv[row] * (A[row] @ W) ) ----------------
// Block tile 64 x OUT (small smem -> 2-3 CTAs/SM), K=128, 8 warps.
// Warp layout: WARPS_M=2 (WM=32, MT=2), WARPS_N=4 (WN=OUT/4, NT=WN/8).
template<int OUT>
__global__ __launch_bounds__(256) void gemm_tc_kernel(
    const float* __restrict__ A, const float* __restrict__ W,
    const int* __restrict__ deg, __half* __restrict__ hp, int n)
{
    constexpr int K       = 128;
    constexpr int TILE_M  = 64;
    constexpr int WARPS_M = 2;
    constexpr int WM      = TILE_M / WARPS_M;  // 32
    constexpr int WN      = OUT / 4;           // 32 or 16
    constexpr int MT      = WM / 16;           // 2
    constexpr int NT      = WN / 8;            // 4 or 2
    constexpr int SX      = K + 4;
    constexpr int SW      = OUT + 4;

    extern __shared__ uint32_t smem[];
    uint32_t* Xs = smem;                  // [TILE_M][SX] tf32
    uint32_t* Ws = smem + TILE_M * SX;    // [K][SW]      tf32

    const int t    = threadIdx.x;
    const int lane = t & 31;
    const int wid  = t >> 5;
    const int wm   = wid % WARPS_M;
    const int wn   = wid / WARPS_M;
    const int lr   = lane >> 2;   // 0..7
    const int lc   = lane & 3;    // 0..3

    const int row0 = blockIdx.x * TILE_M;

    for (int i = t; i < K * (OUT / 4); i += 256) {
        int r  = i / (OUT / 4);
        int c4 = i % (OUT / 4);
        float4 v = ((const float4*)W)[(size_t)r * (OUT / 4) + c4];
        uint32_t* p = &Ws[r * SW + c4 * 4];
        p[0] = f2tf(v.x); p[1] = f2tf(v.y); p[2] = f2tf(v.z); p[3] = f2tf(v.w);
    }
    for (int i = t; i < TILE_M * (K / 4); i += 256) {
        int r  = i / (K / 4);
        int c4 = i % (K / 4);
        int gr = row0 + r;
        float4 v = (gr < n) ? ((const float4*)A)[(size_t)gr * (K / 4) + c4]
                            : make_float4(0.f, 0.f, 0.f, 0.f);
        uint32_t* p = &Xs[r * SX + c4 * 4];
        p[0] = f2tf(v.x); p[1] = f2tf(v.y); p[2] = f2tf(v.z); p[3] = f2tf(v.w);
    }
    __syncthreads();

    float d[MT][NT][4];
#pragma unroll
    for (int mt = 0; mt < MT; mt++)
#pragma unroll
        for (int nt = 0; nt < NT; nt++) {
            d[mt][nt][0] = 0.f; d[mt][nt][1] = 0.f;
            d[mt][nt][2] = 0.f; d[mt][nt][3] = 0.f;
        }

    const int r0 = wm * WM;
    const int c0 = wn * WN;

#pragma unroll
    for (int k0 = 0; k0 < K; k0 += 8) {
        uint32_t b[NT][2];
#pragma unroll
        for (int nt = 0; nt < NT; nt++) {
            int bc = c0 + nt * 8 + lr;
            b[nt][0] = Ws[(k0 + lc)     * SW + bc];
            b[nt][1] = Ws[(k0 + lc + 4) * SW + bc];
        }
#pragma unroll
        for (int mt = 0; mt < MT; mt++) {
            int ar = r0 + mt * 16 + lr;
            uint32_t a0 = Xs[ar       * SX + k0 + lc];
            uint32_t a1 = Xs[(ar + 8) * SX + k0 + lc];
            uint32_t a2 = Xs[ar       * SX + k0 + lc + 4];
            uint32_t a3 = Xs[(ar + 8) * SX + k0 + lc + 4];
#pragma unroll
            for (int nt = 0; nt < NT; nt++)
                mma_tf32(d[mt][nt], a0, a1, a2, a3, b[nt][0], b[nt][1]);
        }
    }

#pragma unroll
    for (int mt = 0; mt < MT; mt++) {
        int gr0 = row0 + r0 + mt * 16 + lr;
        int gr1 = gr0 + 8;
        float dv0 = (gr0 < n) ? rsqrtf((float)(deg[gr0] + 1)) : 0.f;
        float dv1 = (gr1 < n) ? rsqrtf((float)(deg[gr1] + 1)) : 0.f;
#pragma unroll
        for (int nt = 0; nt < NT; nt++) {
            int gc = c0 + nt * 8 + 2 * lc;
            if (gr0 < n) {
                __half2 h = __floats2half2_rn(d[mt][nt][0] * dv0, d[mt][nt][1] * dv0);
                ((uint32_t*)hp)[(size_t)gr0 * (OUT / 2) + gc / 2] = *(uint32_t*)&h;
            }
            if (gr1 < n) {
                __half2 h = __floats2half2_rn(d[mt][nt][2] * dv1, d[mt][nt][3] * dv1);
                ((uint32_t*)hp)[(size_t)gr1 * (OUT / 2) + gc / 2] = *(uint32_t*)&h;
            }
        }
    }
}

// ---------------- aggregate: out[d] = act(dinv[d]*(hp[d] + sum_src hp[src]) + b) ----------------
__device__ __forceinline__ void acc8(float* a, uint4 v) {
    const __half2* ph = (const __half2*)&v;
#pragma unroll
    for (int j = 0; j < 4; j++) {
        float2 f = __half22float2(ph[j]);
        a[2 * j]     += f.x;
        a[2 * j + 1] += f.y;
    }
}

template<int F, bool RELU>
__global__ __launch_bounds__(256) void aggregate_kernel(
    const int* __restrict__ rowptr, const int* __restrict__ col,
    const __half* __restrict__ hp, const int* __restrict__ deg,
    const float* __restrict__ b, float* __restrict__ out, int n)
{
    constexpr int LPR = F / 8;        // lanes per node row (16 or 8)
    constexpr int SUB = 32 / LPR;     // nodes per warp (2 or 4)
    const int warp = (blockIdx.x * blockDim.x + threadIdx.x) >> 5;
    const int lane = threadIdx.x & 31;
    const int node = warp * SUB + lane / LPR;
    const int li   = lane % LPR;
    if (node >= n) return;

    const uint4* hp4 = (const uint4*)hp;

    float a0[8] = {0,0,0,0,0,0,0,0};
    float a1[8] = {0,0,0,0,0,0,0,0};

    acc8(a0, hp4[(size_t)node * LPR + li]);   // self-loop term (prescaled)

    int e  = rowptr[node];
    int e1 = rowptr[node + 1];

    for (; e + 8 <= e1; e += 8) {
        int s0 = __ldg(&col[e]);
        int s1 = __ldg(&col[e + 1]);
        int s2 = __ldg(&col[e + 2]);
        int s3 = __ldg(&col[e + 3]);
        int s4 = __ldg(&col[e + 4]);
        int s5 = __ldg(&col[e + 5]);
        int s6 = __ldg(&col[e + 6]);
        int s7 = __ldg(&col[e + 7]);
        uint4 v0 = hp4[(size_t)s0 * LPR + li];
        uint4 v1 = hp4[(size_t)s1 * LPR + li];
        uint4 v2 = hp4[(size_t)s2 * LPR + li];
        uint4 v3 = hp4[(size_t)s3 * LPR + li];
        uint4 v4 = hp4[(size_t)s4 * LPR + li];
        uint4 v5 = hp4[(size_t)s5 * LPR + li];
        uint4 v6 = hp4[(size_t)s6 * LPR + li];
        uint4 v7 = hp4[(size_t)s7 * LPR + li];
        acc8(a0, v0); acc8(a1, v1); acc8(a0, v2); acc8(a1, v3);
        acc8(a0, v4); acc8(a1, v5); acc8(a0, v6); acc8(a1, v7);
    }
    for (; e + 2 <= e1; e += 2) {
        int s0 = __ldg(&col[e]);
        int s1 = __ldg(&col[e + 1]);
        uint4 v0 = hp4[(size_t)s0 * LPR + li];
        uint4 v1 = hp4[(size_t)s1 * LPR + li];
        acc8(a0, v0); acc8(a1, v1);
    }
    for (; e < e1; e++) {
        acc8(a0, hp4[(size_t)__ldg(&col[e]) * LPR + li]);
    }
#pragma unroll
    for (int j = 0; j < 8; j++) a0[j] += a1[j];

    float dv = rsqrtf((float)(deg[node] + 1));
    const float4* b4 = (const float4*)b;
    float4 bv0 = b4[li * 2];
    float4 bv1 = b4[li * 2 + 1];
    float4 o0, o1;
    o0.x = fmaf(a0[0], dv, bv0.x);
    o0.y = fmaf(a0[1], dv, bv0.y);
    o0.z = fmaf(a0[2], dv, bv0.z);
    o0.w = fmaf(a0[3], dv, bv0.w);
    o1.x = fmaf(a0[4], dv, bv1.x);
    o1.y = fmaf(a0[5], dv, bv1.y);
    o1.z = fmaf(a0[6], dv, bv1.z);
    o1.w = fmaf(a0[7], dv, bv1.w);
    if (RELU) {
        o0.x = fmaxf(o0.x, 0.f); o0.y = fmaxf(o0.y, 0.f);
        o0.z = fmaxf(o0.z, 0.f); o0.w = fmaxf(o0.w, 0.f);
        o1.x = fmaxf(o1.x, 0.f); o1.y = fmaxf(o1.y, 0.f);
        o1.z = fmaxf(o1.z, 0.f); o1.w = fmaxf(o1.w, 0.f);
    }
    float4* out4 = (float4*)out;
    out4[(size_t)node * (F / 4) + li * 2]     = o0;
    out4[(size_t)node * (F / 4) + li * 2 + 1] = o1;
}

// ---------------- launcher ----------------
extern "C" void kernel_launch(void* const* d_in, const int* in_sizes, int n_in,
                              void* d_out, int out_size)
{
    const float* x   = (const float*)d_in[0];
    const int*   ei  = (const int*)d_in[1];     // int32 OR int64 raw words (probed)
    const float* W1  = (const float*)d_in[2];
    const float* b1  = (const float*)d_in[3];
    const float* W2  = (const float*)d_in[4];
    const float* b2  = (const float*)d_in[5];
    float*       out = (float*)d_out;

    const int n = in_sizes[0] / FIN;   // 50000
    const int e = in_sizes[1] / 2;     // 800000

    void *p_is64, *p_deg, *p_rowptr, *p_cursor, *p_col, *p_part, *p_hp1, *p_h1, *p_hp2;
    cudaGetSymbolAddress(&p_is64,   g_is64);
    cudaGetSymbolAddress(&p_deg,    g_deg);
    cudaGetSymbolAddress(&p_rowptr, g_rowptr);
    cudaGetSymbolAddress(&p_cursor, g_cursor);
    cudaGetSymbolAddress(&p_col,    g_col);
    cudaGetSymbolAddress(&p_part,   g_part);
    cudaGetSymbolAddress(&p_hp1,    g_hp1);
    cudaGetSymbolAddress(&p_h1,     g_h1);
    cudaGetSymbolAddress(&p_hp2,    g_hp2);
    int*    is64   = (int*)p_is64;
    int*    deg    = (int*)p_deg;
    int*    rowptr = (int*)p_rowptr;
    int*    cursor = (int*)p_cursor;
    int*    col    = (int*)p_col;
    int*    part   = (int*)p_part;
    __half* hp1    = (__half*)p_hp1;
    float*  h1     = (float*)p_h1;
    __half* hp2    = (__half*)p_hp2;

    // one-time side stream + events (created on first, non-captured, call)
    static cudaStream_t s_side = nullptr;
    static cudaEvent_t  ev_fork = nullptr, ev_join = nullptr;
    if (s_side == nullptr) {
        cudaStreamCreateWithFlags(&s_side, cudaStreamNonBlocking);
        cudaEventCreateWithFlags(&ev_fork, cudaEventDisableTiming);
        cudaEventCreateWithFlags(&ev_join, cudaEventDisableTiming);
    }

    const int smem1 = (64 * (128 + 4) + 128 * (FH + 4)) * (int)sizeof(uint32_t);  // 101376
    const int smem2 = (64 * (128 + 4) + 128 * (FO + 4)) * (int)sizeof(uint32_t);  //  68608
    cudaFuncSetAttribute((const void*)gemm_tc_kernel<FH>, cudaFuncAttributeMaxDynamicSharedMemorySize, smem1);
    cudaFuncSetAttribute((const void*)gemm_tc_kernel<FO>, cudaFuncAttributeMaxDynamicSharedMemorySize, smem2);

    const int nb = (n + 1023) / 1024;

    // ---- main: probe + degrees ----
    cudaMemsetAsync(deg, 0, n * sizeof(int));
    probe_kernel     <<<1, 256>>>(ei, is64);
    count_deg_kernel <<<(e + 255) / 256, 256>>>(ei, e, is64, deg);

    // ---- fork: CSR build on side stream ----
    cudaEventRecord(ev_fork, 0);
    cudaStreamWaitEvent(s_side, ev_fork, 0);
    scan_block_kernel<<<nb, 1024, 0, s_side>>>(deg, n, rowptr, part);
    scan_part_kernel <<<1, 256, 0, s_side>>>(part, nb, rowptr, n);
    add_off_kernel   <<<(n + 255) / 256, 256, 0, s_side>>>(part, n, rowptr, cursor);
    fill_kernel      <<<(e + 255) / 256, 256, 0, s_side>>>(ei, e, is64, cursor, col);
    cudaEventRecord(ev_join, s_side);

    // ---- main: gemm1 (needs only deg) ----
    gemm_tc_kernel<FH><<<(n + 63) / 64, 256, smem1>>>(x, W1, deg, hp1, n);

    // ---- join, then agg1 / gemm2 / agg2 ----
    cudaStreamWaitEvent(0, ev_join, 0);
    {
        int warps = (n + 1) / 2;
        aggregate_kernel<FH, true><<<(warps * 32 + 255) / 256, 256>>>(rowptr, col, hp1, deg, b1, h1, n);
    }
    gemm_tc_kernel<FO><<<(n + 63) / 64, 256, smem2>>>(h1, W2, deg, hp2, n);
    {
        int warps = (n + 3) / 4;
        aggregate_kernel<FO, false><<<(warps * 32 + 255) / 256, 256>>>(rowptr, col, hp2, deg, b2, out, n);
    }
}

// round 11
// speedup vs baseline: 1.9753x; 1.2200x over previous
#include <cuda_runtime.h>
#include <cuda_fp16.h>
#include <cstdint>

#define NV 50000
#define NE 800000
#define FIN 128
#define FH  128
#define FO  64

// ---------------- scratch (no allocs allowed) ----------------
static __device__ int    g_is64;
static __device__ int    g_deg   [NV];
static __device__ int    g_rowptr[NV + 1];
static __device__ int    g_cursor[NV];
static __device__ int    g_col   [NE];
static __device__ int    g_part  [256];
static __device__ __align__(16) __half g_hp1[(size_t)NV * FH];   // dinv-prescaled x@W1   (fp16)
static __device__ __align__(16) __half g_h1 [(size_t)NV * FH];   // layer-1 activation    (fp16)
static __device__ __align__(16) __half g_hp2[(size_t)NV * FO];   // dinv-prescaled h1@W2  (fp16)

// ---------------- edge-index dtype probe ----------------
// If edge_index is int64 (LE, values < 2^31), every odd int32 word is 0.
__global__ void probe_kernel(const int* __restrict__ raw, int* __restrict__ is64) {
    int v = raw[2 * threadIdx.x + 1];
    int any = __syncthreads_or(v != 0);
    if (threadIdx.x == 0) *is64 = (any == 0) ? 1 : 0;
}

// count dst degrees straight from raw edge buffer (deg pre-zeroed)
__global__ void count_deg_kernel(const int* __restrict__ raw, int e,
                                 const int* __restrict__ is64f,
                                 int* __restrict__ deg) {
    int i = blockIdx.x * blockDim.x + threadIdx.x;
    if (i >= e) return;
    int d = (*is64f) ? raw[2 * ((size_t)e + i)] : raw[(size_t)e + i];
    atomicAdd(&deg[d], 1);
}

// ---------------- 3-phase scan ----------------
__global__ void scan_block_kernel(const int* __restrict__ deg, int n,
                                  int* __restrict__ rowptr, int* __restrict__ part)
{
    __shared__ int sm[1024];
    int i = blockIdx.x * 1024 + threadIdx.x;
    int v = (i < n) ? deg[i] : 0;
    sm[threadIdx.x] = v;
    __syncthreads();
    for (int off = 1; off < 1024; off <<= 1) {
        int t = (threadIdx.x >= (unsigned)off) ? sm[threadIdx.x - off] : 0;
        __syncthreads();
        sm[threadIdx.x] += t;
        __syncthreads();
    }
    if (i < n) rowptr[i] = sm[threadIdx.x] - v;      // block-local exclusive
    if (threadIdx.x == 1023) part[blockIdx.x] = sm[1023];
}

__global__ void scan_part_kernel(int* __restrict__ part, int nb,
                                 int* __restrict__ rowptr, int n)
{
    __shared__ int sm[256];
    int v = (threadIdx.x < (unsigned)nb) ? part[threadIdx.x] : 0;
    sm[threadIdx.x] = v;
    __syncthreads();
    for (int off = 1; off < 256; off <<= 1) {
        int t = (threadIdx.x >= (unsigned)off) ? sm[threadIdx.x - off] : 0;
        __syncthreads();
        sm[threadIdx.x] += t;
        __syncthreads();
    }
    if (threadIdx.x < (unsigned)nb) part[threadIdx.x] = sm[threadIdx.x] - v;  // exclusive
    if (threadIdx.x == 0) rowptr[n] = sm[255];
}

__global__ void add_off_kernel(const int* __restrict__ part, int n,
                               int* __restrict__ rowptr, int* __restrict__ cursor)
{
    int i = blockIdx.x * blockDim.x + threadIdx.x;
    if (i < n) {
        int r = rowptr[i] + part[i >> 10];
        rowptr[i] = r;
        cursor[i] = r;
    }
}

// ---------------- CSR fill: col[pos] = src, grouped by dst ----------------
__global__ void fill_kernel(const int* __restrict__ raw, int e,
                            const int* __restrict__ is64f,
                            int* __restrict__ cursor, int* __restrict__ col)
{
    int i = blockIdx.x * blockDim.x + threadIdx.x;
    if (i >= e) return;
    int s, d;
    if (*is64f) {
        s = raw[2 * (size_t)i];
        d = raw[2 * ((size_t)e + i)];
    } else {
        s = raw[i];
        d = raw[(size_t)e + i];
    }
    int pos = atomicAdd(&cursor[d], 1);
    col[pos] = s;
}

// ---------------- fp16 mma helper ----------------
__device__ __forceinline__ void mma_f16(float* d,
    uint32_t a0, uint32_t a1, uint32_t a2, uint32_t a3,
    uint32_t b0, uint32_t b1)
{
    asm volatile("mma.sync.aligned.m16n8k16.row.col.f32.f16.f16.f32 "
        "{%0,%1,%2,%3}, {%4,%5,%6,%7}, {%8,%9}, {%0,%1,%2,%3};"
        : "+f"(d[0]), "+f"(d[1]), "+f"(d[2]), "+f"(d[3])
        : "r"(a0), "r"(a1), "r"(a2), "r"(a3), "r"(b0), "r"(b1));
}

// ---------------- fp16 tensor-core GEMM: hp[row] = fp16( dinv[row] * (A[row] @ W) ) ----------------
// Block tile 64 x OUT, K=128, 8 warps. A fp32 or fp16 per IN_HALF.
// Smem: X as packed half2 words [64][68], W transposed as [OUT][68] (word w = k rows 2w,2w+1).
template<int OUT, bool IN_HALF>
__global__ __launch_bounds__(256) void gemm_f16_kernel(
    const void* __restrict__ Ain, const float* __restrict__ W,
    const int* __restrict__ deg, __half* __restrict__ hp, int n)
{
    constexpr int K       = 128;
    constexpr int TILE_M  = 64;
    constexpr int WARPS_M = 2;
    constexpr int WM      = TILE_M / WARPS_M;  // 32
    constexpr int WN      = OUT / 4;           // 32 or 16
    constexpr int MT      = WM / 16;           // 2
    constexpr int NT      = WN / 8;            // 4 or 2
    constexpr int SK      = K / 2 + 4;         // 68 words; stride%32=4 -> banks 4*lr+lc distinct

    extern __shared__ uint32_t smem[];
    uint32_t* Xs = smem;                  // [TILE_M][SK]
    uint32_t* Wt = smem + TILE_M * SK;    // [OUT][SK]

    const int t    = threadIdx.x;
    const int lane = t & 31;
    const int wid  = t >> 5;
    const int wm   = wid % WARPS_M;
    const int wn   = wid / WARPS_M;
    const int lr   = lane >> 2;   // 0..7
    const int lc   = lane & 3;    // 0..3

    const int row0 = blockIdx.x * TILE_M;

    // W [K][OUT] fp32 -> Wt [OUT][K/2] packed half2 (transpose)
    for (int i = t; i < (K / 2) * OUT; i += 256) {
        int k2 = i / OUT;
        int c  = i % OUT;
        float f0 = W[(size_t)(2 * k2)     * OUT + c];
        float f1 = W[(size_t)(2 * k2 + 1) * OUT + c];
        __half2 h = __floats2half2_rn(f0, f1);
        Wt[c * SK + k2] = *(uint32_t*)&h;
    }
    // X tile -> Xs packed half2
    if (IN_HALF) {
        const uint4* A8 = (const uint4*)Ain;
        for (int i = t; i < TILE_M * (K / 8); i += 256) {
            int r  = i / (K / 8);
            int c8 = i % (K / 8);
            int gr = row0 + r;
            uint32_t* p = &Xs[r * SK + c8 * 4];
            if (gr < n) {
                uint4 v = A8[(size_t)gr * (K / 8) + c8];
                p[0] = v.x; p[1] = v.y; p[2] = v.z; p[3] = v.w;
            } else {
                p[0] = 0; p[1] = 0; p[2] = 0; p[3] = 0;
            }
        }
    } else {
        const float4* A4 = (const float4*)Ain;
        for (int i = t; i < TILE_M * (K / 4); i += 256) {
            int r  = i / (K / 4);
            int c4 = i % (K / 4);
            int gr = row0 + r;
            float4 v = (gr < n) ? A4[(size_t)gr * (K / 4) + c4]
                                : make_float4(0.f, 0.f, 0.f, 0.f);
            __half2 h0 = __floats2half2_rn(v.x, v.y);
            __half2 h1 = __floats2half2_rn(v.z, v.w);
            Xs[r * SK + c4 * 2]     = *(uint32_t*)&h0;
            Xs[r * SK + c4 * 2 + 1] = *(uint32_t*)&h1;
        }
    }
    __syncthreads();

    float d[MT][NT][4];
#pragma unroll
    for (int mt = 0; mt < MT; mt++)
#pragma unroll
        for (int nt = 0; nt < NT; nt++) {
            d[mt][nt][0] = 0.f; d[mt][nt][1] = 0.f;
            d[mt][nt][2] = 0.f; d[mt][nt][3] = 0.f;
        }

    const int r0 = wm * WM;
    const int c0 = wn * WN;

#pragma unroll
    for (int k0 = 0; k0 < K; k0 += 16) {
        const int w0 = k0 / 2;     // word offset of this k-step
        uint32_t b[NT][2];
#pragma unroll
        for (int nt = 0; nt < NT; nt++) {
            int bc = c0 + nt * 8 + lr;
            b[nt][0] = Wt[bc * SK + w0 + lc];
            b[nt][1] = Wt[bc * SK + w0 + 4 + lc];
        }
#pragma unroll
        for (int mt = 0; mt < MT; mt++) {
            int ar = r0 + mt * 16 + lr;
            uint32_t a0 = Xs[ar       * SK + w0 + lc];
            uint32_t a1 = Xs[(ar + 8) * SK + w0 + lc];
            uint32_t a2 = Xs[ar       * SK + w0 + 4 + lc];
            uint32_t a3 = Xs[(ar + 8) * SK + w0 + 4 + lc];
#pragma unroll
            for (int nt = 0; nt < NT; nt++)
                mma_f16(d[mt][nt], a0, a1, a2, a3, b[nt][0], b[nt][1]);
        }
    }

#pragma unroll
    for (int mt = 0; mt < MT; mt++) {
        int gr0 = row0 + r0 + mt * 16 + lr;
        int gr1 = gr0 + 8;
        float dv0 = (gr0 < n) ? rsqrtf((float)(deg[gr0] + 1)) : 0.f;
        float dv1 = (gr1 < n) ? rsqrtf((float)(deg[gr1] + 1)) : 0.f;
#pragma unroll
        for (int nt = 0; nt < NT; nt++) {
            int gc = c0 + nt * 8 + 2 * lc;
            if (gr0 < n) {
                __half2 h = __floats2half2_rn(d[mt][nt][0] * dv0, d[mt][nt][1] * dv0);
                ((uint32_t*)hp)[(size_t)gr0 * (OUT / 2) + gc / 2] = *(uint32_t*)&h;
            }
            if (gr1 < n) {
                __half2 h = __floats2half2_rn(d[mt][nt][2] * dv1, d[mt][nt][3] * dv1);
                ((uint32_t*)hp)[(size_t)gr1 * (OUT / 2) + gc / 2] = *(uint32_t*)&h;
            }
        }
    }
}

// ---------------- aggregate: out[d] = act(dinv[d]*(hp[d] + sum_src hp[src]) + b) ----------------
__device__ __forceinline__ void acc8(float* a, uint4 v) {
    const __half2* ph = (const __half2*)&v;
#pragma unroll
    for (int j = 0; j < 4; j++) {
        float2 f = __half22float2(ph[j]);
        a[2 * j]     += f.x;
        a[2 * j + 1] += f.y;
    }
}

template<int F, bool RELU, bool OUT_HALF>
__global__ __launch_bounds__(256) void aggregate_kernel(
    const int* __restrict__ rowptr, const int* __restrict__ col,
    const __half* __restrict__ hp, const int* __restrict__ deg,
    const float* __restrict__ b, void* __restrict__ out, int n)
{
    constexpr int LPR = F / 8;        // lanes per node row (16 or 8)
    constexpr int SUB = 32 / LPR;     // nodes per warp (2 or 4)
    const int warp = (blockIdx.x * blockDim.x + threadIdx.x) >> 5;
    const int lane = threadIdx.x & 31;
    const int node = warp * SUB + lane / LPR;
    const int li   = lane % LPR;
    if (node >= n) return;

    const uint4* hp4 = (const uint4*)hp;

    float a0[8] = {0,0,0,0,0,0,0,0};
    float a1[8] = {0,0,0,0,0,0,0,0};

    acc8(a0, hp4[(size_t)node * LPR + li]);   // self-loop term (prescaled)

    int e  = rowptr[node];
    int e1 = rowptr[node + 1];

    for (; e + 8 <= e1; e += 8) {
        int s0 = __ldg(&col[e]);
        int s1 = __ldg(&col[e + 1]);
        int s2 = __ldg(&col[e + 2]);
        int s3 = __ldg(&col[e + 3]);
        int s4 = __ldg(&col[e + 4]);
        int s5 = __ldg(&col[e + 5]);
        int s6 = __ldg(&col[e + 6]);
        int s7 = __ldg(&col[e + 7]);
        uint4 v0 = hp4[(size_t)s0 * LPR + li];
        uint4 v1 = hp4[(size_t)s1 * LPR + li];
        uint4 v2 = hp4[(size_t)s2 * LPR + li];
        uint4 v3 = hp4[(size_t)s3 * LPR + li];
        uint4 v4 = hp4[(size_t)s4 * LPR + li];
        uint4 v5 = hp4[(size_t)s5 * LPR + li];
        uint4 v6 = hp4[(size_t)s6 * LPR + li];
        uint4 v7 = hp4[(size_t)s7 * LPR + li];
        acc8(a0, v0); acc8(a1, v1); acc8(a0, v2); acc8(a1, v3);
        acc8(a0, v4); acc8(a1, v5); acc8(a0, v6); acc8(a1, v7);
    }
    for (; e + 2 <= e1; e += 2) {
        int s0 = __ldg(&col[e]);
        int s1 = __ldg(&col[e + 1]);
        uint4 v0 = hp4[(size_t)s0 * LPR + li];
        uint4 v1 = hp4[(size_t)s1 * LPR + li];
        acc8(a0, v0); acc8(a1, v1);
    }
    for (; e < e1; e++) {
        acc8(a0, hp4[(size_t)__ldg(&col[e]) * LPR + li]);
    }
#pragma unroll
    for (int j = 0; j < 8; j++) a0[j] += a1[j];

    float dv = rsqrtf((float)(deg[node] + 1));
    const float4* b4 = (const float4*)b;
    float4 bv0 = b4[li * 2];
    float4 bv1 = b4[li * 2 + 1];
    float o[8];
    o[0] = fmaf(a0[0], dv, bv0.x);
    o[1] = fmaf(a0[1], dv, bv0.y);
    o[2] = fmaf(a0[2], dv, bv0.z);
    o[3] = fmaf(a0[3], dv, bv0.w);
    o[4] = fmaf(a0[4], dv, bv1.x);
    o[5] = fmaf(a0[5], dv, bv1.y);
    o[6] = fmaf(a0[6], dv, bv1.z);
    o[7] = fmaf(a0[7], dv, bv1.w);
    if (RELU) {
#pragma unroll
        for (int j = 0; j < 8; j++) o[j] = fmaxf(o[j], 0.f);
    }
    if (OUT_HALF) {
        __half2 h0 = __floats2half2_rn(o[0], o[1]);
        __half2 h1 = __floats2half2_rn(o[2], o[3]);
        __half2 h2 = __floats2half2_rn(o[4], o[5]);
        __half2 h3 = __floats2half2_rn(o[6], o[7]);
        uint4 pk;
        pk.x = *(uint32_t*)&h0; pk.y = *(uint32_t*)&h1;
        pk.z = *(uint32_t*)&h2; pk.w = *(uint32_t*)&h3;
        ((uint4*)out)[(size_t)node * LPR + li] = pk;
    } else {
        float4* out4 = (float4*)out;
        out4[(size_t)node * (F / 4) + li * 2]     = make_float4(o[0], o[1], o[2], o[3]);
        out4[(size_t)node * (F / 4) + li * 2 + 1] = make_float4(o[4], o[5], o[6], o[7]);
    }
}

// ---------------- launcher ----------------
extern "C" void kernel_launch(void* const* d_in, const int* in_sizes, int n_in,
                              void* d_out, int out_size)
{
    const float* x   = (const float*)d_in[0];
    const int*   ei  = (const int*)d_in[1];     // int32 OR int64 raw words (probed)
    const float* W1  = (const float*)d_in[2];
    const float* b1  = (const float*)d_in[3];
    const float* W2  = (const float*)d_in[4];
    const float* b2  = (const float*)d_in[5];
    float*       out = (float*)d_out;

    const int n = in_sizes[0] / FIN;   // 50000
    const int e = in_sizes[1] / 2;     // 800000

    void *p_is64, *p_deg, *p_rowptr, *p_cursor, *p_col, *p_part, *p_hp1, *p_h1, *p_hp2;
    cudaGetSymbolAddress(&p_is64,   g_is64);
    cudaGetSymbolAddress(&p_deg,    g_deg);
    cudaGetSymbolAddress(&p_rowptr, g_rowptr);
    cudaGetSymbolAddress(&p_cursor, g_cursor);
    cudaGetSymbolAddress(&p_col,    g_col);
    cudaGetSymbolAddress(&p_part,   g_part);
    cudaGetSymbolAddress(&p_hp1,    g_hp1);
    cudaGetSymbolAddress(&p_h1,     g_h1);
    cudaGetSymbolAddress(&p_hp2,    g_hp2);
    int*    is64   = (int*)p_is64;
    int*    deg    = (int*)p_deg;
    int*    rowptr = (int*)p_rowptr;
    int*    cursor = (int*)p_cursor;
    int*    col    = (int*)p_col;
    int*    part   = (int*)p_part;
    __half* hp1    = (__half*)p_hp1;
    __half* h1     = (__half*)p_h1;
    __half* hp2    = (__half*)p_hp2;

    // one-time side stream + events (created on first, non-captured, call)
    static cudaStream_t s_side = nullptr;
    static cudaEvent_t  ev_fork = nullptr, ev_join = nullptr;
    if (s_side == nullptr) {
        cudaStreamCreateWithFlags(&s_side, cudaStreamNonBlocking);
        cudaEventCreateWithFlags(&ev_fork, cudaEventDisableTiming);
        cudaEventCreateWithFlags(&ev_join, cudaEventDisableTiming);
    }

    constexpr int SK = 128 / 2 + 4;   // 68
    const int smem1 = (64 * SK + FH * SK) * (int)sizeof(uint32_t);  // 52224
    const int smem2 = (64 * SK + FO * SK) * (int)sizeof(uint32_t);  // 34816
    cudaFuncSetAttribute((const void*)gemm_f16_kernel<FH, false>, cudaFuncAttributeMaxDynamicSharedMemorySize, smem1);
    cudaFuncSetAttribute((const void*)gemm_f16_kernel<FO, true>,  cudaFuncAttributeMaxDynamicSharedMemorySize, smem2);

    const int nb = (n + 1023) / 1024;

    // ---- main: probe + degrees ----
    cudaMemsetAsync(deg, 0, n * sizeof(int));
    probe_kernel     <<<1, 256>>>(ei, is64);
    count_deg_kernel <<<(e + 255) / 256, 256>>>(ei, e, is64, deg);

    // ---- fork: CSR build on side stream ----
    cudaEventRecord(ev_fork, 0);
    cudaStreamWaitEvent(s_side, ev_fork, 0);
    scan_block_kernel<<<nb, 1024, 0, s_side>>>(deg, n, rowptr, part);
    scan_part_kernel <<<1, 256, 0, s_side>>>(part, nb, rowptr, n);
    add_off_kernel   <<<(n + 255) / 256, 256, 0, s_side>>>(part, n, rowptr, cursor);
    fill_kernel      <<<(e + 255) / 256, 256, 0, s_side>>>(ei, e, is64, cursor, col);
    cudaEventRecord(ev_join, s_side);

    // ---- main: gemm1 (needs only deg) ----
    gemm_f16_kernel<FH, false><<<(n + 63) / 64, 256, smem1>>>(x, W1, deg, hp1, n);

    // ---- join, then agg1 / gemm2 / agg2 ----
    cudaStreamWaitEvent(0, ev_join, 0);
    {
        int warps = (n + 1) / 2;
        aggregate_kernel<FH, true, true><<<(warps * 32 + 255) / 256, 256>>>(rowptr, col, hp1, deg, b1, h1, n);
    }
    gemm_f16_kernel<FO, true><<<(n + 63) / 64, 256, smem2>>>(h1, W2, deg, hp2, n);
    {
        int warps = (n + 3) / 4;
        aggregate_kernel<FO, false, false><<<(warps * 32 + 255) / 256, 256>>>(rowptr, col, hp2, deg, b2, out, n);
    }
}